// round 9
// baseline (speedup 1.0000x reference)
#include <cuda_runtime.h>
#include <cuda_fp16.h>
#include <cstdint>

#define DEVINL __device__ __forceinline__

DEVINL uint32_t smem_u32(const void* p) {
    uint32_t a;
    asm("{ .reg .u64 t; cvta.to.shared.u64 t, %1; cvt.u32.u64 %0, t; }"
        : "=r"(a) : "l"(p));
    return a;
}

// 128B-row swizzle — verified conflict-free for ldmatrix.x4
#define SWZ(o) ((o) ^ (((o) >> 3) & 0x70))

DEVINL void ldsm_x4(uint32_t& r0, uint32_t& r1, uint32_t& r2, uint32_t& r3, uint32_t addr) {
    asm volatile("ldmatrix.sync.aligned.m8n8.x4.shared.b16 {%0,%1,%2,%3}, [%4];"
                 : "=r"(r0), "=r"(r1), "=r"(r2), "=r"(r3) : "r"(addr));
}

DEVINL void mma_16816(float* c, uint32_t a0, uint32_t a1, uint32_t a2, uint32_t a3,
                      uint32_t b0, uint32_t b1) {
    asm volatile(
        "mma.sync.aligned.m16n8k16.row.col.f32.f16.f16.f32 "
        "{%0,%1,%2,%3}, {%4,%5,%6,%7}, {%8,%9}, {%0,%1,%2,%3};"
        : "+f"(c[0]), "+f"(c[1]), "+f"(c[2]), "+f"(c[3])
        : "r"(a0), "r"(a1), "r"(a2), "r"(a3), "r"(b0), "r"(b1));
}

DEVINL void cp_async16(uint32_t smem_addr, const void* gptr) {
    asm volatile("cp.async.cg.shared.global [%0], [%1], 16;"
                 :: "r"(smem_addr), "l"(gptr));
}
#define CP_COMMIT() asm volatile("cp.async.commit_group;" ::: "memory")
#define CP_WAIT(n)  asm volatile("cp.async.wait_group %0;" :: "n"(n) : "memory")

// ============================================================================
// Problem constants
// ============================================================================
static constexpr int N_ROWS  = 262144;
static constexpr int M_TILE  = 128;
static constexpr int N_CTAS  = N_ROWS / M_TILE;  // 2048
static constexpr int THREADS = 512;              // 16 warps, 4m x 4n

// fp16 transposed weights (scratch via device globals)
__device__ __align__(16) __half w1h_g[512 * 1024];  // [N=512][K=1024]
__device__ __align__(16) __half w2h_g[256 * 512];   // [N=256][K=512]

// ---------------- SMEM layout (bytes) ----------------
static constexpr int SM_W0  = 0;       // 2048 f32 ([2][1024]) = 8192
static constexpr int SM_B0  = 8192;    // 1024 f32             = 4096
static constexpr int SM_B1  = 12288;   // 512 f32              = 2048
static constexpr int SM_B2  = 14336;   // 256 f32              = 1024
static constexpr int SM_W3  = 15360;   // 768 f32              = 3072 -> 18432
static constexpr int SM_H2  = 18432;   // 8 x 16KB blocks (h2 fp16 SWZ128) -> 149504
//   A double buffer OVERLAYS H2 blocks 4-5 (written only at pass-1 epilogue)
static constexpr int SM_A0  = SM_H2 + 4 * 16384;   // A buf 0 (128x64 fp16)
static constexpr int SM_A1B = SM_H2 + 5 * 16384;   // A buf 1
static constexpr int SM_BR  = 149504;  // 2 x 32KB B stages (256x64 fp16) -> 215040
static constexpr int SM_PART = SM_BR;  // overlay (B dead at layer 3)
static constexpr int SMEM_TOTAL = 215040;

static constexpr int N_CHUNKS = 40;    // 16 + 16 (layer1 passes) + 8 (layer2)

// ============================================================================
// Prep: transpose + fp16-convert W1, W2
// ============================================================================
__global__ void prep_weights(const float* __restrict__ W1, const float* __restrict__ W2) {
    int i = blockIdx.x * blockDim.x + threadIdx.x;
    if (i < 512 * 1024) {
        int n = i >> 10, k = i & 1023;
        w1h_g[i] = __float2half_rn(W1[k * 512 + n]);
    } else {
        int j = i - 512 * 1024;
        if (j < 256 * 512) {
            int n = j >> 9, k = j & 511;
            w2h_g[j] = __float2half_rn(W2[k * 256 + n]);
        }
    }
}

// gmem source for 64-wide B chunk g; task row rowb (0..255), segment seg (0..7)
DEVINL const __half* chunk_src(int g, int rowb, int seg) {
    if (g < 16)  return w1h_g + rowb * 1024 + g * 64 + seg * 8;
    if (g < 32)  return w1h_g + (256 + rowb) * 1024 + (g - 16) * 64 + seg * 8;
    return w2h_g + rowb * 512 + (g - 32) * 64 + seg * 8;
}

// ============================================================================
// Fused MLP: one CTA = 128 rows through all 4 layers
// ============================================================================
__global__ __launch_bounds__(THREADS, 1) void fused_mlp_kernel(
    const float* __restrict__ coord,
    const float* __restrict__ W0, const float* __restrict__ b0,
    const float* __restrict__ b1, const float* __restrict__ b2,
    const float* __restrict__ W3, const float* __restrict__ b3,
    float* __restrict__ out)
{
    extern __shared__ char smem[];
    const uint32_t sb = smem_u32(smem);
    const int tid  = threadIdx.x;
    const int wid  = tid >> 5;
    const int lane = tid & 31;
    const int row0 = blockIdx.x * M_TILE;

    float* sW0 = (float*)(smem + SM_W0);
    float* sB0 = (float*)(smem + SM_B0);
    float* sB1 = (float*)(smem + SM_B1);
    float* sB2 = (float*)(smem + SM_B2);
    float* sW3 = (float*)(smem + SM_W3);
    float* sPart = (float*)(smem + SM_PART);

    // ---- issue B chunk 0 immediately ----
    const int rb  = tid >> 3;        // 0..63 (stride 64 over ii)
    const int seg = tid & 7;
    #pragma unroll
    for (int ii = 0; ii < 4; ++ii)
        cp_async16(sb + SM_BR + SWZ((uint32_t)((rb + 64 * ii) * 128 + seg * 16)),
                   chunk_src(0, rb + 64 * ii, seg));
    CP_COMMIT();

    // ---- preload constants ----
    for (int i = tid; i < 2048; i += THREADS) sW0[i] = W0[i];
    for (int i = tid; i < 1024; i += THREADS) sB0[i] = b0[i];
    if (tid < 512) sB1[tid] = b1[tid];
    if (tid < 256) sB2[tid] = b2[tid];
    for (int i = tid; i < 768; i += THREADS) sW3[i] = W3[i];

    // layer0 producer: thread owns row rp, 16-col slab kk0 within 64-col chunk
    const int rp  = tid >> 2;            // 0..127
    const int kk0 = (tid & 3) * 16;      // 0,16,32,48
    const float cxr = coord[(row0 + rp) * 2];
    const float cyr = coord[(row0 + rp) * 2 + 1];

    __syncthreads();  // consts visible

    // produce A chunk 0 into buf 0
    {
        char* ab = smem + SM_A0;
        #pragma unroll
        for (int u = 0; u < 8; ++u) {
            const int k = kk0 + 2 * u;   // k0 = 0
            float v0 = fmaxf(fmaf(cxr, sW0[k],     fmaf(cyr, sW0[1024 + k],     sB0[k])),     0.f);
            float v1 = fmaxf(fmaf(cxr, sW0[k + 1], fmaf(cyr, sW0[1024 + k + 1], sB0[k + 1])), 0.f);
            *(__half2*)(ab + SWZ((uint32_t)(rp * 128 + k * 2))) = __floats2half2_rn(v0, v1);
        }
    }

    // ---- per-warp tile geometry: 4 row groups x 4 col groups, 32x64 tiles ----
    const int m0  = (wid >> 2) * 32;
    const int n0w = (wid & 3) * 64;

    const int a_row = (lane & 7) + ((lane >> 3) & 1) * 8;
    const int a_kby = ((lane >> 4) & 1) * 16;
    const int b_row = (lane & 7) + ((lane >> 4) & 1) * 8;
    const int b_kby = ((lane >> 3) & 1) * 16;

    float acc[2][8][4];
    #pragma unroll
    for (int i = 0; i < 2; ++i)
        #pragma unroll
        for (int j = 0; j < 8; ++j)
            #pragma unroll
            for (int q = 0; q < 4; ++q) acc[i][j][q] = 0.f;

    // ------------------------------------------------------------------------
    // Unified 40-chunk pipeline: g = 0..15 L1/pass0, 16..31 L1/pass1, 32..39 L2
    // ------------------------------------------------------------------------
    for (int g = 0; g < N_CHUNKS; ++g) {
        __syncthreads();  // prior MMA reads of bnxt/abuf((g+1)&1) complete

        if (g + 1 < N_CHUNKS) {
            const uint32_t bn = sb + SM_BR + ((g + 1) & 1) * 32768;
            #pragma unroll
            for (int ii = 0; ii < 4; ++ii)
                cp_async16(bn + SWZ((uint32_t)((rb + 64 * ii) * 128 + seg * 16)),
                           chunk_src(g + 1, rb + 64 * ii, seg));
        }
        CP_COMMIT();
        CP_WAIT(1);       // B(g) arrived (newest group = B(g+1) may fly)
        __syncthreads();  // B(g) + A(g) visible to all

        const uint32_t bs = sb + SM_BR + (g & 1) * 32768;

        if (g < 32) {
            // ---- layer-1 MMA on chunk g (A from double buffer) ----
            const uint32_t ab = sb + ((g & 1) ? SM_A1B : SM_A0);
            #pragma unroll
            for (int ks = 0; ks < 4; ++ks) {
                const int kby = ks * 32;
                uint32_t A0[4], A1f[4];
                ldsm_x4(A0[0], A0[1], A0[2], A0[3],
                        ab + SWZ((uint32_t)((m0 + a_row) * 128 + kby + a_kby)));
                ldsm_x4(A1f[0], A1f[1], A1f[2], A1f[3],
                        ab + SWZ((uint32_t)((m0 + 16 + a_row) * 128 + kby + a_kby)));
                #pragma unroll
                for (int j2 = 0; j2 < 4; ++j2) {
                    uint32_t bb[4];
                    ldsm_x4(bb[0], bb[1], bb[2], bb[3],
                            bs + SWZ((uint32_t)((n0w + j2 * 16 + b_row) * 128 + kby + b_kby)));
                    mma_16816(acc[0][2 * j2],     A0[0],  A0[1],  A0[2],  A0[3],  bb[0], bb[1]);
                    mma_16816(acc[0][2 * j2 + 1], A0[0],  A0[1],  A0[2],  A0[3],  bb[2], bb[3]);
                    mma_16816(acc[1][2 * j2],     A1f[0], A1f[1], A1f[2], A1f[3], bb[0], bb[1]);
                    mma_16816(acc[1][2 * j2 + 1], A1f[0], A1f[1], A1f[2], A1f[3], bb[2], bb[3]);
                }
            }

            // ---- produce A(g+1) concurrently with this chunk's MMA ----
            if (g + 1 < 32) {
                const int k0p = ((g + 1) & 15) * 64;
                char* abP = smem + (((g + 1) & 1) ? SM_A1B : SM_A0);
                #pragma unroll
                for (int u = 0; u < 8; ++u) {
                    const int kl = kk0 + 2 * u;
                    const int k  = k0p + kl;
                    float v0 = fmaxf(fmaf(cxr, sW0[k],     fmaf(cyr, sW0[1024 + k],     sB0[k])),     0.f);
                    float v1 = fmaxf(fmaf(cxr, sW0[k + 1], fmaf(cyr, sW0[1024 + k + 1], sB0[k + 1])), 0.f);
                    *(__half2*)(abP + SWZ((uint32_t)(rp * 128 + kl * 2))) =
                        __floats2half2_rn(v0, v1);
                }
            }

            // ---- epilogues at pass ends: h2 = relu(D1 + b1) -> H2 blocks ----
            if (g == 15 || g == 31) {
                if (g == 31) __syncthreads();  // A-buf overlay: all reads done
                const int cn = (g == 31 ? 256 : 0) + n0w;
                #pragma unroll
                for (int i = 0; i < 2; ++i) {
                    const int r = m0 + i * 16 + (lane >> 2);
                    #pragma unroll
                    for (int j = 0; j < 8; ++j) {
                        const int c = cn + j * 8 + (lane & 3) * 2;
                        const float bz0 = sB1[c], bz1 = sB1[c + 1];
                        float v0 = fmaxf(acc[i][j][0] + bz0, 0.f);
                        float v1 = fmaxf(acc[i][j][1] + bz1, 0.f);
                        float v2 = fmaxf(acc[i][j][2] + bz0, 0.f);
                        float v3 = fmaxf(acc[i][j][3] + bz1, 0.f);
                        const int blk = c >> 6, jj = (c & 63) * 2;
                        *(__half2*)(smem + SM_H2 + blk * 16384 + SWZ((uint32_t)(r * 128 + jj))) =
                            __floats2half2_rn(v0, v1);
                        *(__half2*)(smem + SM_H2 + blk * 16384 + SWZ((uint32_t)((r + 8) * 128 + jj))) =
                            __floats2half2_rn(v2, v3);
                        acc[i][j][0] = acc[i][j][1] = acc[i][j][2] = acc[i][j][3] = 0.f;
                    }
                }
            }
        } else {
            // ---- layer-2 MMA on chunk g (A from resident H2 block g-32) ----
            const uint32_t ab = sb + SM_H2 + (g - 32) * 16384;
            #pragma unroll
            for (int ks = 0; ks < 4; ++ks) {
                const int kby = ks * 32;
                uint32_t A0[4], A1f[4];
                ldsm_x4(A0[0], A0[1], A0[2], A0[3],
                        ab + SWZ((uint32_t)((m0 + a_row) * 128 + kby + a_kby)));
                ldsm_x4(A1f[0], A1f[1], A1f[2], A1f[3],
                        ab + SWZ((uint32_t)((m0 + 16 + a_row) * 128 + kby + a_kby)));
                #pragma unroll
                for (int j2 = 0; j2 < 4; ++j2) {
                    uint32_t bb[4];
                    ldsm_x4(bb[0], bb[1], bb[2], bb[3],
                            bs + SWZ((uint32_t)((n0w + j2 * 16 + b_row) * 128 + kby + b_kby)));
                    mma_16816(acc[0][2 * j2],     A0[0],  A0[1],  A0[2],  A0[3],  bb[0], bb[1]);
                    mma_16816(acc[0][2 * j2 + 1], A0[0],  A0[1],  A0[2],  A0[3],  bb[2], bb[3]);
                    mma_16816(acc[1][2 * j2],     A1f[0], A1f[1], A1f[2], A1f[3], bb[0], bb[1]);
                    mma_16816(acc[1][2 * j2 + 1], A1f[0], A1f[1], A1f[2], A1f[3], bb[2], bb[3]);
                }
            }
        }
    }

    // ------------------------------------------------------------------------
    // Layer 3: out = relu(D2 + b2) @ W3 + b3 from register fragments
    // ------------------------------------------------------------------------
    float p[2][2][3];
    #pragma unroll
    for (int i = 0; i < 2; ++i)
        #pragma unroll
        for (int h = 0; h < 2; ++h)
            p[i][h][0] = p[i][h][1] = p[i][h][2] = 0.f;

    #pragma unroll
    for (int i = 0; i < 2; ++i) {
        #pragma unroll
        for (int j = 0; j < 8; ++j) {
            const int c = n0w + j * 8 + (lane & 3) * 2;
            #pragma unroll
            for (int q = 0; q < 4; ++q) {
                const int h  = q >> 1;
                const int cc = c + (q & 1);
                const float v = fmaxf(acc[i][j][q] + sB2[cc], 0.f);
                p[i][h][0] = fmaf(v, sW3[cc * 3 + 0], p[i][h][0]);
                p[i][h][1] = fmaf(v, sW3[cc * 3 + 1], p[i][h][1]);
                p[i][h][2] = fmaf(v, sW3[cc * 3 + 2], p[i][h][2]);
            }
        }
    }
    #pragma unroll
    for (int i = 0; i < 2; ++i)
        #pragma unroll
        for (int h = 0; h < 2; ++h)
            #pragma unroll
            for (int o = 0; o < 3; ++o) {
                float v = p[i][h][o];
                v += __shfl_xor_sync(0xffffffffu, v, 1);
                v += __shfl_xor_sync(0xffffffffu, v, 2);
                p[i][h][o] = v;
            }
    __syncthreads();  // all B-ring reads done; safe to overlay sPart
    if ((lane & 3) == 0) {
        const int cg = wid & 3;
        #pragma unroll
        for (int i = 0; i < 2; ++i)
            #pragma unroll
            for (int h = 0; h < 2; ++h) {
                const int r = m0 + i * 16 + (lane >> 2) + 8 * h;
                sPart[cg * 384 + r * 3 + 0] = p[i][h][0];
                sPart[cg * 384 + r * 3 + 1] = p[i][h][1];
                sPart[cg * 384 + r * 3 + 2] = p[i][h][2];
            }
    }
    __syncthreads();

    if (tid < 384) {
        const int r = tid / 3, o = tid - r * 3;
        out[(row0 + r) * 3 + o] =
            sPart[tid] + sPart[384 + tid] + sPart[768 + tid] + sPart[1152 + tid] + b3[o];
    }
}

// ============================================================================
// Launch
// ============================================================================
extern "C" void kernel_launch(void* const* d_in, const int* in_sizes, int n_in,
                              void* d_out, int out_size) {
    const float* coord = (const float*)d_in[0];
    const float* W0    = (const float*)d_in[1];
    const float* b0    = (const float*)d_in[2];
    const float* W1    = (const float*)d_in[3];
    const float* b1    = (const float*)d_in[4];
    const float* W2    = (const float*)d_in[5];
    const float* b2    = (const float*)d_in[6];
    const float* W3    = (const float*)d_in[7];
    const float* b3    = (const float*)d_in[8];
    float* out = (float*)d_out;

    static bool attr_set = false;
    if (!attr_set) {
        cudaFuncSetAttribute(fused_mlp_kernel,
                             cudaFuncAttributeMaxDynamicSharedMemorySize, SMEM_TOTAL);
        attr_set = true;
    }

    const int prep_elems = 512 * 1024 + 256 * 512;
    prep_weights<<<(prep_elems + 255) / 256, 256>>>(W1, W2);
    fused_mlp_kernel<<<N_CTAS, THREADS, SMEM_TOTAL>>>(coord, W0, b0, b1, b2, W3, b3, out);
}

// round 10
// speedup vs baseline: 1.2606x; 1.2606x over previous
#include <cuda_runtime.h>
#include <cuda_fp16.h>
#include <cstdint>

#define DEVINL __device__ __forceinline__

DEVINL uint32_t smem_u32(const void* p) {
    uint32_t a;
    asm("{ .reg .u64 t; cvta.to.shared.u64 t, %1; cvt.u32.u64 %0, t; }"
        : "=r"(a) : "l"(p));
    return a;
}

// 128B-row swizzle — verified conflict-free for ldmatrix.x4
#define SWZ(o) ((o) ^ (((o) >> 3) & 0x70))

DEVINL void ldsm_x4(uint32_t& r0, uint32_t& r1, uint32_t& r2, uint32_t& r3, uint32_t addr) {
    asm volatile("ldmatrix.sync.aligned.m8n8.x4.shared.b16 {%0,%1,%2,%3}, [%4];"
                 : "=r"(r0), "=r"(r1), "=r"(r2), "=r"(r3) : "r"(addr));
}

DEVINL void mma_16816(float* c, uint32_t a0, uint32_t a1, uint32_t a2, uint32_t a3,
                      uint32_t b0, uint32_t b1) {
    asm volatile(
        "mma.sync.aligned.m16n8k16.row.col.f32.f16.f16.f32 "
        "{%0,%1,%2,%3}, {%4,%5,%6,%7}, {%8,%9}, {%0,%1,%2,%3};"
        : "+f"(c[0]), "+f"(c[1]), "+f"(c[2]), "+f"(c[3])
        : "r"(a0), "r"(a1), "r"(a2), "r"(a3), "r"(b0), "r"(b1));
}

DEVINL void cp_async16(uint32_t smem_addr, const void* gptr) {
    asm volatile("cp.async.cg.shared.global [%0], [%1], 16;"
                 :: "r"(smem_addr), "l"(gptr));
}
#define CP_COMMIT() asm volatile("cp.async.commit_group;" ::: "memory")
#define CP_WAIT(n)  asm volatile("cp.async.wait_group %0;" :: "n"(n) : "memory")

// ============================================================================
// Problem constants
// ============================================================================
static constexpr int N_ROWS  = 262144;
static constexpr int M_TILE  = 128;
static constexpr int N_CTAS  = N_ROWS / M_TILE;  // 2048
static constexpr int THREADS = 256;              // 8 warps, 2m x 4n, 64x64 tiles

// fp16 transposed weights (scratch via device globals)
__device__ __align__(16) __half w1h_g[512 * 1024];  // [N=512][K=1024]
__device__ __align__(16) __half w2h_g[256 * 512];   // [N=256][K=512]

// ---------------- SMEM layout (bytes) — as in the 969us kernel --------------
static constexpr int SM_COORD = 0;       // 128 x float2          = 1024
static constexpr int SM_W0    = 1024;    // 2048 f32              = 8192
static constexpr int SM_B0    = 9216;    // 1024 f32              = 4096
static constexpr int SM_B1    = 13312;   // 512 f32               = 2048
static constexpr int SM_B2    = 15360;   // 256 f32               = 1024
static constexpr int SM_W3    = 16384;   // 768 f32               = 3072  -> 19456
static constexpr int SM_H2    = 19456;   // 8 blocks x 16KB       = 131072 -> 150528
static constexpr int SM_A1    = 150528;  // 128x64 fp16 SWZ128    = 16384 -> 166912
static constexpr int SM_PART  = 150528;  // overlay on A1 (dead at layer 3)
static constexpr int SM_BCH0  = 166912;  // 256x64 fp16 SWZ128    = 32768 -> 199680
static constexpr int SM_BCH1  = 199680;  // 256x64 fp16 SWZ128    = 32768 -> 232448
static constexpr int SMEM_TOTAL = 232448;

// ============================================================================
// Prep: transpose + fp16-convert W1, W2
// ============================================================================
__global__ void prep_weights(const float* __restrict__ W1, const float* __restrict__ W2) {
    int i = blockIdx.x * blockDim.x + threadIdx.x;
    if (i < 512 * 1024) {
        int n = i >> 10, k = i & 1023;
        w1h_g[i] = __float2half_rn(W1[k * 512 + n]);
    } else {
        int j = i - 512 * 1024;
        if (j < 256 * 512) {
            int n = j >> 9, k = j & 511;
            w2h_g[j] = __float2half_rn(W2[k * 256 + n]);
        }
    }
}

// ============================================================================
// Fused MLP: one CTA = 128 rows through all 4 layers; 8 warps, 64x64 tiles
// ============================================================================
__global__ __launch_bounds__(THREADS, 1) void fused_mlp_kernel(
    const float* __restrict__ coord,
    const float* __restrict__ W0, const float* __restrict__ b0,
    const float* __restrict__ b1, const float* __restrict__ b2,
    const float* __restrict__ W3, const float* __restrict__ b3,
    float* __restrict__ out)
{
    extern __shared__ char smem[];
    const uint32_t sb = smem_u32(smem);
    const int tid  = threadIdx.x;
    const int wid  = tid >> 5;
    const int lane = tid & 31;
    const int row0 = blockIdx.x * M_TILE;

    float* sCoord = (float*)(smem + SM_COORD);
    float* sW0    = (float*)(smem + SM_W0);
    float* sB0    = (float*)(smem + SM_B0);
    float* sB1    = (float*)(smem + SM_B1);
    float* sB2    = (float*)(smem + SM_B2);
    float* sW3    = (float*)(smem + SM_W3);
    float* sPart  = (float*)(smem + SM_PART);

    // ---- preload constants + coord tile ----
    if (tid < 256) sCoord[tid] = coord[row0 * 2 + tid];
    for (int i = tid; i < 2048; i += THREADS) sW0[i] = W0[i];
    for (int i = tid; i < 1024; i += THREADS) sB0[i] = b0[i];
    for (int i = tid; i < 512;  i += THREADS) sB1[i] = b1[i];
    if (tid < 256) sB2[tid] = b2[tid];
    for (int i = tid; i < 768;  i += THREADS) sW3[i] = W3[i];

    // ---- per-warp tile geometry: 2 row groups x 4 col groups, 64x64 tiles ----
    const int m0  = (wid >> 2) * 64;    // warp row base (64 rows)
    const int n0w = (wid & 3) * 64;     // warp col base within a 256-col pass

    const int a_row = (lane & 7) + ((lane >> 3) & 1) * 8;
    const int a_kby = ((lane >> 4) & 1) * 16;
    const int b_row = (lane & 7) + ((lane >> 4) & 1) * 8;
    const int b_kby = ((lane >> 3) & 1) * 16;

    // layer0 producer: thread owns row rp (2 threads/row), 4 x 16B segments
    const int rp   = tid >> 1;           // 0..127
    const int shalf = (tid & 1) * 4;     // segment base: 0 or 4
    const float cxr = sCoord[0];         // placeholder; real loads below after sync

    // B-chunk async copy: 2048 x 16B per chunk over 256 threads -> 8 each
    const int rowb = tid >> 3;           // 0..31, stride 32 across ii
    const int seg  = tid & 7;

    // prologue: first B1 chunk (pass 0, kc 0) into buffer 0
    {
        const __half* src = w1h_g + rowb * 1024 + seg * 8;
        #pragma unroll
        for (int ii = 0; ii < 8; ++ii)
            cp_async16(sb + SM_BCH0 + SWZ((uint32_t)((rowb + 32 * ii) * 128 + seg * 16)),
                       src + (32 * ii) * 1024);
        CP_COMMIT();
    }
    __syncthreads();   // consts + coord visible
    const float cx = sCoord[2 * rp], cy = sCoord[2 * rp + 1];
    (void)cxr;

    // =========================================================================
    // Layer 0+1: D1[128,512] = relu(coord@W0+b0) @ W1, two 256-col passes
    // =========================================================================
    for (int pass = 0; pass < 2; ++pass) {
        float acc[4][8][4];
        #pragma unroll
        for (int i = 0; i < 4; ++i)
            #pragma unroll
            for (int j = 0; j < 8; ++j)
                #pragma unroll
                for (int q = 0; q < 4; ++q) acc[i][j][q] = 0.f;

        for (int kc = 0; kc < 16; ++kc) {
            const uint32_t bcur = (kc & 1) ? SM_BCH1 : SM_BCH0;
            const uint32_t bnxt = (kc & 1) ? SM_BCH0 : SM_BCH1;
            __syncthreads();  // buffer-reuse fence (prev MMA reads done)

            const bool last = (pass == 1) && (kc == 15);
            if (kc < 15) {
                const int j0n = (kc + 1) * 64;
                const __half* src = w1h_g + (pass * 256 + rowb) * 1024 + j0n + seg * 8;
                #pragma unroll
                for (int ii = 0; ii < 8; ++ii)
                    cp_async16(sb + bnxt + SWZ((uint32_t)((rowb + 32 * ii) * 128 + seg * 16)),
                               src + (32 * ii) * 1024);
                CP_COMMIT();
            } else if (pass == 0) {
                const __half* src = w1h_g + (256 + rowb) * 1024 + seg * 8;
                #pragma unroll
                for (int ii = 0; ii < 8; ++ii)
                    cp_async16(sb + bnxt + SWZ((uint32_t)((rowb + 32 * ii) * 128 + seg * 16)),
                               src + (32 * ii) * 1024);
                CP_COMMIT();
            }

            // --- layer0: h1[:, kc*64 .. +63] -> fp16 A-chunk; vector 16B stores
            //     thread: row rp, segments shalf..shalf+3 (8 cols each) ---
            {
                const int j0 = kc * 64;
                #pragma unroll
                for (int u = 0; u < 4; ++u) {
                    const int s = shalf + u;
                    const int c0 = j0 + s * 8;
                    __half2 hv[4];
                    #pragma unroll
                    for (int e = 0; e < 4; ++e) {
                        const int k = c0 + e * 2;
                        float v0 = fmaxf(fmaf(cx, sW0[k],     fmaf(cy, sW0[1024 + k],     sB0[k])),     0.f);
                        float v1 = fmaxf(fmaf(cx, sW0[k + 1], fmaf(cy, sW0[1024 + k + 1], sB0[k + 1])), 0.f);
                        hv[e] = __floats2half2_rn(v0, v1);
                    }
                    *(uint4*)(smem + SM_A1 + SWZ((uint32_t)(rp * 128 + s * 16))) =
                        *(uint4*)hv;
                }
            }

            if (last) { CP_WAIT(0); } else { CP_WAIT(1); }
            __syncthreads();  // A stores + B arrival visible

            // --- 4 k-steps of mma: 4 A frags, 4 B frag pairs, 32 mma per ks ---
            #pragma unroll
            for (int ks = 0; ks < 4; ++ks) {
                const int kby = ks * 32;
                uint32_t Af[4][4];
                #pragma unroll
                for (int mi = 0; mi < 4; ++mi)
                    ldsm_x4(Af[mi][0], Af[mi][1], Af[mi][2], Af[mi][3],
                            sb + SM_A1 + SWZ((uint32_t)((m0 + mi * 16 + a_row) * 128 + kby + a_kby)));
                #pragma unroll
                for (int j2 = 0; j2 < 4; ++j2) {
                    uint32_t bb[4];
                    ldsm_x4(bb[0], bb[1], bb[2], bb[3],
                            bcur + sb + SWZ((uint32_t)((n0w + j2 * 16 + b_row) * 128 + kby + b_kby)));
                    #pragma unroll
                    for (int mi = 0; mi < 4; ++mi) {
                        mma_16816(acc[mi][2 * j2],     Af[mi][0], Af[mi][1], Af[mi][2], Af[mi][3], bb[0], bb[1]);
                        mma_16816(acc[mi][2 * j2 + 1], Af[mi][0], Af[mi][1], Af[mi][2], Af[mi][3], bb[2], bb[3]);
                    }
                }
            }

            if (last) {
                // prologue for layer-2 (kc=15 -> bcur=BCH1, BCH0 free)
                const __half* src = w2h_g + rowb * 512 + seg * 8;
                #pragma unroll
                for (int ii = 0; ii < 8; ++ii)
                    cp_async16(sb + SM_BCH0 + SWZ((uint32_t)((rowb + 32 * ii) * 128 + seg * 16)),
                               src + (32 * ii) * 512);
                CP_COMMIT();
            }
        }

        // --- epilogue: h2 = relu(D1 + b1) -> fp16 H2 (8 x 16KB blocks) ---
        const int cn = pass * 256 + n0w;
        #pragma unroll
        for (int mi = 0; mi < 4; ++mi) {
            const int r = m0 + mi * 16 + (lane >> 2);
            #pragma unroll
            for (int j = 0; j < 8; ++j) {
                const int c = cn + j * 8 + (lane & 3) * 2;
                const float bz0 = sB1[c], bz1 = sB1[c + 1];
                float v0 = fmaxf(acc[mi][j][0] + bz0, 0.f);
                float v1 = fmaxf(acc[mi][j][1] + bz1, 0.f);
                float v2 = fmaxf(acc[mi][j][2] + bz0, 0.f);
                float v3 = fmaxf(acc[mi][j][3] + bz1, 0.f);
                const int blk = c >> 6, jj = (c & 63) * 2;
                *(__half2*)(smem + SM_H2 + blk * 16384 + SWZ((uint32_t)(r * 128 + jj))) =
                    __floats2half2_rn(v0, v1);
                *(__half2*)(smem + SM_H2 + blk * 16384 + SWZ((uint32_t)((r + 8) * 128 + jj))) =
                    __floats2half2_rn(v2, v3);
            }
        }
    }

    // =========================================================================
    // Layer 2: D2[128,256] = h2[128,512] @ W2 (A resident in SM_H2)
    // =========================================================================
    float acc2[4][8][4];
    #pragma unroll
    for (int i = 0; i < 4; ++i)
        #pragma unroll
        for (int j = 0; j < 8; ++j)
            #pragma unroll
            for (int q = 0; q < 4; ++q) acc2[i][j][q] = 0.f;

    for (int kc = 0; kc < 8; ++kc) {
        const uint32_t bcur = (kc & 1) ? SM_BCH1 : SM_BCH0;
        const uint32_t bnxt = (kc & 1) ? SM_BCH0 : SM_BCH1;
        __syncthreads();  // buffer-reuse fence + (kc==0) h2-write fence

        if (kc < 7) {
            const __half* src = w2h_g + rowb * 512 + (kc + 1) * 64 + seg * 8;
            #pragma unroll
            for (int ii = 0; ii < 8; ++ii)
                cp_async16(sb + bnxt + SWZ((uint32_t)((rowb + 32 * ii) * 128 + seg * 16)),
                           src + (32 * ii) * 512);
            CP_COMMIT();
            CP_WAIT(1);
        } else {
            CP_WAIT(0);
        }
        __syncthreads();

        const uint32_t abase = sb + SM_H2 + kc * 16384;
        #pragma unroll
        for (int ks = 0; ks < 4; ++ks) {
            const int kby = ks * 32;
            uint32_t Af[4][4];
            #pragma unroll
            for (int mi = 0; mi < 4; ++mi)
                ldsm_x4(Af[mi][0], Af[mi][1], Af[mi][2], Af[mi][3],
                        abase + SWZ((uint32_t)((m0 + mi * 16 + a_row) * 128 + kby + a_kby)));
            #pragma unroll
            for (int j2 = 0; j2 < 4; ++j2) {
                uint32_t bb[4];
                ldsm_x4(bb[0], bb[1], bb[2], bb[3],
                        bcur + sb + SWZ((uint32_t)((n0w + j2 * 16 + b_row) * 128 + kby + b_kby)));
                #pragma unroll
                for (int mi = 0; mi < 4; ++mi) {
                    mma_16816(acc2[mi][2 * j2],     Af[mi][0], Af[mi][1], Af[mi][2], Af[mi][3], bb[0], bb[1]);
                    mma_16816(acc2[mi][2 * j2 + 1], Af[mi][0], Af[mi][1], Af[mi][2], Af[mi][3], bb[2], bb[3]);
                }
            }
        }
    }

    // =========================================================================
    // Layer 3: out = relu(D2 + b2) @ W3 + b3, from register fragments
    // =========================================================================
    float p[4][2][3];
    #pragma unroll
    for (int mi = 0; mi < 4; ++mi)
        #pragma unroll
        for (int h = 0; h < 2; ++h)
            p[mi][h][0] = p[mi][h][1] = p[mi][h][2] = 0.f;

    #pragma unroll
    for (int mi = 0; mi < 4; ++mi) {
        #pragma unroll
        for (int j = 0; j < 8; ++j) {
            const int c = n0w + j * 8 + (lane & 3) * 2;
            #pragma unroll
            for (int q = 0; q < 4; ++q) {
                const int h  = q >> 1;
                const int cc = c + (q & 1);
                const float v = fmaxf(acc2[mi][j][q] + sB2[cc], 0.f);
                p[mi][h][0] = fmaf(v, sW3[cc * 3 + 0], p[mi][h][0]);
                p[mi][h][1] = fmaf(v, sW3[cc * 3 + 1], p[mi][h][1]);
                p[mi][h][2] = fmaf(v, sW3[cc * 3 + 2], p[mi][h][2]);
            }
        }
    }
    #pragma unroll
    for (int mi = 0; mi < 4; ++mi)
        #pragma unroll
        for (int h = 0; h < 2; ++h)
            #pragma unroll
            for (int o = 0; o < 3; ++o) {
                float v = p[mi][h][o];
                v += __shfl_xor_sync(0xffffffffu, v, 1);
                v += __shfl_xor_sync(0xffffffffu, v, 2);
                p[mi][h][o] = v;
            }
    __syncthreads();  // all fragment reads done; safe to overlay sPart on A1
    if ((lane & 3) == 0) {
        const int cg = wid & 3;
        #pragma unroll
        for (int mi = 0; mi < 4; ++mi)
            #pragma unroll
            for (int h = 0; h < 2; ++h) {
                const int r = m0 + mi * 16 + (lane >> 2) + 8 * h;
                sPart[cg * 384 + r * 3 + 0] = p[mi][h][0];
                sPart[cg * 384 + r * 3 + 1] = p[mi][h][1];
                sPart[cg * 384 + r * 3 + 2] = p[mi][h][2];
            }
    }
    __syncthreads();

    {
        if (tid < 384) {
            // first 256 threads cover 0..255; re-use low 128 threads for 256..383
            const int r = tid / 3, o = tid - r * 3;
            out[(row0 + r) * 3 + o] =
                sPart[tid] + sPart[384 + tid] + sPart[768 + tid] + sPart[1152 + tid] + b3[o];
        }
        const int e2 = tid + 256;
        if (tid < 128) {
            const int r = e2 / 3, o = e2 - r * 3;
            out[(row0 + r) * 3 + o] =
                sPart[e2] + sPart[384 + e2] + sPart[768 + e2] + sPart[1152 + e2] + b3[o];
        }
    }
}

// ============================================================================
// Launch
// ============================================================================
extern "C" void kernel_launch(void* const* d_in, const int* in_sizes, int n_in,
                              void* d_out, int out_size) {
    const float* coord = (const float*)d_in[0];
    const float* W0    = (const float*)d_in[1];
    const float* b0    = (const float*)d_in[2];
    const float* W1    = (const float*)d_in[3];
    const float* b1    = (const float*)d_in[4];
    const float* W2    = (const float*)d_in[5];
    const float* b2    = (const float*)d_in[6];
    const float* W3    = (const float*)d_in[7];
    const float* b3    = (const float*)d_in[8];
    float* out = (float*)d_out;

    static bool attr_set = false;
    if (!attr_set) {
        cudaFuncSetAttribute(fused_mlp_kernel,
                             cudaFuncAttributeMaxDynamicSharedMemorySize, SMEM_TOTAL);
        attr_set = true;
    }

    const int prep_elems = 512 * 1024 + 256 * 512;
    prep_weights<<<(prep_elems + 255) / 256, 256>>>(W1, W2);
    fused_mlp_kernel<<<N_CTAS, THREADS, SMEM_TOTAL>>>(coord, W0, b0, b1, b2, W3, b3, out);
}